// round 16
// baseline (speedup 1.0000x reference)
#include <cuda_runtime.h>
#include <cuda_bf16.h>

// Problem constants
#define PN   64
#define PTC  256
#define PK   32
#define PTK  64
#define PD   256
#define D4   (PD/4)          // 64 float4 per row
#define FULL_T (PTK + PTC)   // 320

#define NB_CTX  PN                          // 64 ctx pool+gather blocks (first!)
#define NB_MEGA (NB_CTX + PN * PK)          // 64 + 2048 = 2112

// Scratch (device globals — no allocation allowed)
__device__ float g_ctx_use[PN * PD];
__device__ float g_know_use[PN * PK * PD];

// ck_mask dtype probe: jax bool may arrive as 1-byte bool or int32.
__device__ __forceinline__ bool ck_mask_at(const unsigned char* p, int idx) {
    unsigned int w0 = *(const unsigned int*)p;
    if ((w0 & 0xFFFFFF00u) != 0u) {
        return p[idx] != 0;                          // int8 bool layout
    } else {
        return ((const int*)p)[idx] != 0;            // int32 layout
    }
}

// 8-wide batched accumulate (know path): 8 independent LDG.128.CG, then FMAs.
__device__ __forceinline__ void batch8(const float4* __restrict__ e4,
                                       const int* __restrict__ toks,
                                       int t0, int j,
                                       float4& acc, float& lenf)
{
    int tk[8];
    #pragma unroll
    for (int i = 0; i < 8; i++) tk[i] = toks[t0 + i];
    float4 v[8];
    #pragma unroll
    for (int i = 0; i < 8; i++) v[i] = __ldcg(&e4[(size_t)tk[i] * D4 + j]);
    #pragma unroll
    for (int i = 0; i < 8; i++) {
        float w = (tk[i] != 0) ? 1.0f : 0.0f;
        acc.x = fmaf(w, v[i].x, acc.x);
        acc.y = fmaf(w, v[i].y, acc.y);
        acc.z = fmaf(w, v[i].z, acc.z);
        acc.w = fmaf(w, v[i].w, acc.w);
        lenf += w;
    }
}

// ---------------------------------------------------------------------------
// Mega kernel (proven R10 version), two roles:
//   b in [0, 64):      ctx pooling FUSED with ctx-row output gather.
//   b in [64, 2112):   know pooling (kb = b-64).
// ---------------------------------------------------------------------------
__global__ __launch_bounds__(256, 4)
void mega_kernel(const int* __restrict__ src_tokens,
                 const int* __restrict__ know_tokens,
                 const unsigned char* __restrict__ ckm,
                 const float* __restrict__ embed,
                 float* __restrict__ out_enc,
                 float* __restrict__ out_mask)
{
    __shared__ int    toks[PTC];
    __shared__ float4 part[4][D4];     // 4 KB
    __shared__ float  lenp[4];

    const int tid = threadIdx.x;
    const int j   = tid & 63;
    const int tq  = tid >> 6;
    const int b   = blockIdx.x;
    const float4* __restrict__ e4 = (const float4*)embed;

    float4 acc = make_float4(0.f, 0.f, 0.f, 0.f);
    float  lenf = 0.f;
    float* dst;

    if (b < NB_CTX) {
        // ---- ctx pooling + fused output gather ----
        const int n = b;
        toks[tid] = src_tokens[n * PTC + tid];
        __syncthreads();

        out_mask[(size_t)n * FULL_T + PTK + tid] = (toks[tid] != 0) ? 1.0f : 0.0f;

        float4* __restrict__ oe4 = (float4*)out_enc;
        const int t0 = tq * 64;
        #pragma unroll
        for (int bt = 0; bt < 8; bt++) {
            int tk[8];
            #pragma unroll
            for (int i = 0; i < 8; i++) tk[i] = toks[t0 + bt * 8 + i];
            float4 v[8];
            #pragma unroll
            for (int i = 0; i < 8; i++) v[i] = __ldcg(&e4[(size_t)tk[i] * D4 + j]);
            #pragma unroll
            for (int i = 0; i < 8; i++) {
                const float w = (tk[i] != 0) ? 1.0f : 0.0f;
                acc.x = fmaf(w, v[i].x, acc.x);
                acc.y = fmaf(w, v[i].y, acc.y);
                acc.z = fmaf(w, v[i].z, acc.z);
                acc.w = fmaf(w, v[i].w, acc.w);
                lenf += w;
                const size_t r = (size_t)n * FULL_T + PTK + t0 + bt * 8 + i;
                __stcs(&oe4[r * D4 + j],
                       make_float4(w * v[i].x, w * v[i].y, w * v[i].z, w * v[i].w));
            }
        }
        dst = g_ctx_use + (size_t)n * PD;
    } else {
        // ---- know pooling ----
        const int kb = b - NB_CTX;          // 0 .. 2047
        if (tid < PTK) toks[tid] = know_tokens[(size_t)kb * PTK + tid];
        __syncthreads();
        const float cmv = ck_mask_at(ckm, kb) ? 1.0f : 0.0f;

        const int t0 = tq * 16;
        batch8(e4, toks, t0,     j, acc, lenf);
        batch8(e4, toks, t0 + 8, j, acc, lenf);

        acc.x *= cmv; acc.y *= cmv; acc.z *= cmv; acc.w *= cmv;
        lenf *= cmv;
        dst = g_know_use + (size_t)kb * PD;
    }

    part[tq][j] = acc;
    if (j == 0) lenp[tq] = lenf;
    __syncthreads();

    if (tq == 0) {
        float4 p0 = part[0][j], p1 = part[1][j], p2 = part[2][j], p3 = part[3][j];
        float4 a = make_float4(p0.x + p1.x + p2.x + p3.x,
                               p0.y + p1.y + p2.y + p3.y,
                               p0.z + p1.z + p2.z + p3.z,
                               p0.w + p1.w + p2.w + p3.w);
        float L = lenp[0] + lenp[1] + lenp[2] + lenp[3];
        float s = rsqrtf(256.0f * fmaxf(L, 1.0f));
        ((float4*)dst)[j] = make_float4(a.x * s, a.y * s, a.z * s, a.w * s);
    }
}

// ---------------------------------------------------------------------------
// Tail: 4 blocks per n (256 blocks). PDL. The prolog (runs while mega drains)
// stages ALL input-only data this block could need: the 512 candidate tokens
// (every k's 16 rows for this part) and all 32 resolved mask bits — so after
// cudaGridDependencySynchronize() + argmax there are NO dependent global
// loads left except the embed gathers themselves.
// ---------------------------------------------------------------------------
__global__ __launch_bounds__(256)
void tail_kernel(const int* __restrict__ know_tokens,
                 const unsigned char* __restrict__ ckm,
                 const int* __restrict__ cs_ids,
                 const int* __restrict__ use_cs_ids,
                 const float* __restrict__ embed,
                 float* __restrict__ out_enc,
                 float* __restrict__ out_mask,
                 float* __restrict__ out_ck_attn)
{
    const int n    = blockIdx.x >> 2;
    const int prt  = blockIdx.x & 3;
    const int tid  = threadIdx.x;
    const int wid  = tid >> 5;
    const int lane = tid & 31;
    const int j    = tid & 63;
    const int tq   = tid >> 6;
    __shared__ float scores[PK];
    __shared__ int   cand[PK][16];     // candidate tokens: all k, this part's rows
    __shared__ unsigned char mk[PK];   // resolved mask bits
    __shared__ int   cs_sh;

    // ---- PDL prolog: input-only staging (overlaps mega's drain) ----
    const int use = *use_cs_ids;
    const int cs_id_n = cs_ids[n];
    const int tbase = prt * 16;
    // 512 candidate tokens: k = tid>>4 covers 16 k's per 256 threads, 2 passes
    #pragma unroll
    for (int h = 0; h < 2; h++) {
        const int k = (tid >> 4) + h * 16;
        const int t = tid & 15;
        cand[k][t] = know_tokens[((size_t)n * PK + k) * PTK + tbase + t];
    }
    if (tid < PK) mk[tid] = ck_mask_at(ckm, n * PK + tid) ? 1 : 0;
    __syncthreads();

    // Wait for mega's g_ctx_use / g_know_use to be published.
    cudaGridDependencySynchronize();

    // ---- scores (redundant across the 4 parts; data is L2-hot) ----
    const float* __restrict__ cu = g_ctx_use + (size_t)n * PD;
    float cureg[8];
    #pragma unroll
    for (int c = 0; c < 8; c++) cureg[c] = cu[lane + 32 * c];

    #pragma unroll
    for (int kk = 0; kk < 4; kk++) {
        const int k = wid + kk * 8;
        const float* __restrict__ ku = g_know_use + ((size_t)n * PK + k) * PD;
        float p = 0.f;
        #pragma unroll
        for (int c = 0; c < 8; c++) p = fmaf(ku[lane + 32 * c], cureg[c], p);
        #pragma unroll
        for (int o = 16; o; o >>= 1) p += __shfl_xor_sync(0xFFFFFFFFu, p, o);
        if (lane == 0) scores[k] = p;
    }
    __syncthreads();

    if (tid == 0) {
        int best = 0;
        float bv = -__int_as_float(0x7f800000);  // -inf
        #pragma unroll
        for (int k = 0; k < PK; k++) {
            float v = mk[k] ? scores[k] : -__int_as_float(0x7f800000);
            if (v > bv) { bv = v; best = k; }   // first-max matches jnp.argmax
        }
        cs_sh = use ? cs_id_n : best;
    }
    if (prt == 0 && tid < PK) {
        out_ck_attn[n * PK + tid] = mk[tid] ? scores[tid] : 0.0f;
    }
    __syncthreads();

    // ---- gather this part's 16 selected knowledge rows (tokens in smem) ----
    const int cs = cs_sh;
    const bool cmn = mk[cs] != 0;
    const float4* __restrict__ e4 = (const float4*)embed;

    int   rows[4];
    float ws[4];
    float4 v[4];
    #pragma unroll
    for (int i = 0; i < 4; i++) {
        const int t = tq + 4 * i;              // local row 0..15
        const int tok = cand[cs][t];
        const bool m = cmn && (tok != 0);
        ws[i]   = m ? 1.0f : 0.0f;
        rows[i] = m ? tok : 0;
    }
    #pragma unroll
    for (int i = 0; i < 4; i++) v[i] = __ldcg(&e4[(size_t)rows[i] * D4 + j]);
    #pragma unroll
    for (int i = 0; i < 4; i++) {
        const int t = tq + 4 * i;
        const size_t r = (size_t)n * FULL_T + tbase + t;
        __stcs(&((float4*)out_enc)[r * D4 + j],
               make_float4(ws[i] * v[i].x, ws[i] * v[i].y,
                           ws[i] * v[i].z, ws[i] * v[i].w));
    }
    if (tid < 16) {
        const int tok = cand[cs][tid];
        out_mask[(size_t)n * FULL_T + tbase + tid] = (cmn && tok != 0) ? 1.0f : 0.0f;
    }
}

// ---------------------------------------------------------------------------
extern "C" void kernel_launch(void* const* d_in, const int* in_sizes, int n_in,
                              void* d_out, int out_size)
{
    const int*           src_tokens  = (const int*)d_in[0];            // [N,TC]
    const int*           know_tokens = (const int*)d_in[1];            // [N,K,TK]
    const unsigned char* ck_mask     = (const unsigned char*)d_in[2];  // [N,K] bool
    const int*           cs_ids      = (const int*)d_in[3];            // [N]
    const int*           use_cs_ids  = (const int*)d_in[4];            // scalar
    const float*         embed       = (const float*)d_in[5];          // [V,D]

    float* out = (float*)d_out;
    float* out_enc     = out;                                   // N*320*256
    float* out_mask    = out + (size_t)PN * FULL_T * PD;        // N*320
    float* out_ck_attn = out_mask + (size_t)PN * FULL_T;        // N*K

    mega_kernel<<<NB_MEGA, 256>>>(src_tokens, know_tokens, ck_mask, embed,
                                  out_enc, out_mask);

    // Tail via PDL: launches while mega drains; waits inside the kernel.
    cudaLaunchAttribute attrs[1];
    attrs[0].id = cudaLaunchAttributeProgrammaticStreamSerialization;
    attrs[0].val.programmaticStreamSerializationAllowed = 1;

    cudaLaunchConfig_t cfg = {};
    cfg.gridDim  = dim3(PN * 4, 1, 1);
    cfg.blockDim = dim3(256, 1, 1);
    cfg.dynamicSmemBytes = 0;
    cfg.stream = 0;                    // legacy default stream (capture target)
    cfg.attrs = attrs;
    cfg.numAttrs = 1;

    cudaError_t err = cudaLaunchKernelEx(&cfg, tail_kernel,
                                         know_tokens, ck_mask, cs_ids, use_cs_ids,
                                         embed, out_enc, out_mask, out_ck_attn);
    if (err != cudaSuccess) {
        // Fallback: plain launch (cudaGridDependencySynchronize is a no-op
        // when there is no programmatic dependency).
        tail_kernel<<<PN * 4, 256>>>(know_tokens, ck_mask, cs_ids, use_cs_ids,
                                     embed, out_enc, out_mask, out_ck_attn);
    }
}

// round 17
// speedup vs baseline: 1.1044x; 1.1044x over previous
#include <cuda_runtime.h>
#include <cuda_bf16.h>

// Problem constants
#define PN   64
#define PTC  256
#define PK   32
#define PTK  64
#define PD   256
#define D4   (PD/4)          // 64 float4 per row
#define FULL_T (PTK + PTC)   // 320

#define NB_CTX  PN                          // 64 ctx pool+gather blocks (first!)
#define NB_MEGA (NB_CTX + PN * PK)          // 64 + 2048 = 2112

// Scratch (device globals — no allocation allowed)
__device__ float g_ctx_use[PN * PD];
__device__ float g_know_use[PN * PK * PD];

// ck_mask dtype probe: jax bool may arrive as 1-byte bool or int32.
__device__ __forceinline__ bool ck_mask_at(const unsigned char* p, int idx) {
    unsigned int w0 = *(const unsigned int*)p;
    if ((w0 & 0xFFFFFF00u) != 0u) {
        return p[idx] != 0;                          // int8 bool layout
    } else {
        return ((const int*)p)[idx] != 0;            // int32 layout
    }
}

// 8-wide batched accumulate (know path): 8 independent LDG.128.CG, then FMAs.
__device__ __forceinline__ void batch8(const float4* __restrict__ e4,
                                       const int* __restrict__ toks,
                                       int t0, int j,
                                       float4& acc, float& lenf)
{
    int tk[8];
    #pragma unroll
    for (int i = 0; i < 8; i++) tk[i] = toks[t0 + i];
    float4 v[8];
    #pragma unroll
    for (int i = 0; i < 8; i++) v[i] = __ldcg(&e4[(size_t)tk[i] * D4 + j]);
    #pragma unroll
    for (int i = 0; i < 8; i++) {
        float w = (tk[i] != 0) ? 1.0f : 0.0f;
        acc.x = fmaf(w, v[i].x, acc.x);
        acc.y = fmaf(w, v[i].y, acc.y);
        acc.z = fmaf(w, v[i].z, acc.z);
        acc.w = fmaf(w, v[i].w, acc.w);
        lenf += w;
    }
}

// ---------------------------------------------------------------------------
// Mega kernel, two roles:
//   b in [0, 64):      ctx pooling FUSED with ctx-row output gather: every
//                      embed fragment loaded for pooling is also written
//                      (masked) to full_enc — no redundant ctx re-reads.
//   b in [64, 2112):   know pooling (kb = b-64).
// 256 threads, j = tid & 63 (float4 column), tq = tid >> 6 (token group).
// ---------------------------------------------------------------------------
__global__ __launch_bounds__(256, 4)
void mega_kernel(const int* __restrict__ src_tokens,
                 const int* __restrict__ know_tokens,
                 const unsigned char* __restrict__ ckm,
                 const float* __restrict__ embed,
                 float* __restrict__ out_enc,
                 float* __restrict__ out_mask)
{
    __shared__ int    toks[PTC];
    __shared__ float4 part[4][D4];     // 4 KB
    __shared__ float  lenp[4];

    const int tid = threadIdx.x;
    const int j   = tid & 63;
    const int tq  = tid >> 6;
    const int b   = blockIdx.x;
    const float4* __restrict__ e4 = (const float4*)embed;

    float4 acc = make_float4(0.f, 0.f, 0.f, 0.f);
    float  lenf = 0.f;
    float* dst;

    if (b < NB_CTX) {
        // ---- ctx pooling + fused output gather ----
        const int n = b;
        toks[tid] = src_tokens[n * PTC + tid];
        __syncthreads();

        out_mask[(size_t)n * FULL_T + PTK + tid] = (toks[tid] != 0) ? 1.0f : 0.0f;

        float4* __restrict__ oe4 = (float4*)out_enc;
        const int t0 = tq * 64;
        #pragma unroll
        for (int bt = 0; bt < 8; bt++) {
            int tk[8];
            #pragma unroll
            for (int i = 0; i < 8; i++) tk[i] = toks[t0 + bt * 8 + i];
            float4 v[8];
            #pragma unroll
            for (int i = 0; i < 8; i++) v[i] = __ldcg(&e4[(size_t)tk[i] * D4 + j]);
            #pragma unroll
            for (int i = 0; i < 8; i++) {
                const float w = (tk[i] != 0) ? 1.0f : 0.0f;
                acc.x = fmaf(w, v[i].x, acc.x);
                acc.y = fmaf(w, v[i].y, acc.y);
                acc.z = fmaf(w, v[i].z, acc.z);
                acc.w = fmaf(w, v[i].w, acc.w);
                lenf += w;
                const size_t r = (size_t)n * FULL_T + PTK + t0 + bt * 8 + i;
                __stcs(&oe4[r * D4 + j],
                       make_float4(w * v[i].x, w * v[i].y, w * v[i].z, w * v[i].w));
            }
        }
        dst = g_ctx_use + (size_t)n * PD;
    } else {
        // ---- know pooling ----
        const int kb = b - NB_CTX;          // 0 .. 2047
        if (tid < PTK) toks[tid] = know_tokens[(size_t)kb * PTK + tid];
        __syncthreads();
        const float cmv = ck_mask_at(ckm, kb) ? 1.0f : 0.0f;

        const int t0 = tq * 16;
        batch8(e4, toks, t0,     j, acc, lenf);
        batch8(e4, toks, t0 + 8, j, acc, lenf);

        acc.x *= cmv; acc.y *= cmv; acc.z *= cmv; acc.w *= cmv;
        lenf *= cmv;
        dst = g_know_use + (size_t)kb * PD;
    }

    part[tq][j] = acc;
    if (j == 0) lenp[tq] = lenf;
    __syncthreads();

    if (tq == 0) {
        float4 p0 = part[0][j], p1 = part[1][j], p2 = part[2][j], p3 = part[3][j];
        float4 a = make_float4(p0.x + p1.x + p2.x + p3.x,
                               p0.y + p1.y + p2.y + p3.y,
                               p0.z + p1.z + p2.z + p3.z,
                               p0.w + p1.w + p2.w + p3.w);
        float L = lenp[0] + lenp[1] + lenp[2] + lenp[3];
        float s = rsqrtf(256.0f * fmaxf(L, 1.0f));
        ((float4*)dst)[j] = make_float4(a.x * s, a.y * s, a.z * s, a.w * s);
    }
}

// ---------------------------------------------------------------------------
// Tail: 4 blocks per n (256 blocks). PDL: blocks launch while mega drains,
// then wait at cudaGridDependencySynchronize() before touching its outputs.
// Prolog is MINIMAL (two scalar loads only) — staging more input there was
// measured to steal L2 bandwidth from mega's drain (R16 regression).
// Each block redundantly computes the 32 scores + argmax (L2-hot), then
// gathers its 16 of the 64 selected knowledge rows. Part 0 writes ck_attn.
// ---------------------------------------------------------------------------
__global__ __launch_bounds__(256)
void tail_kernel(const int* __restrict__ know_tokens,
                 const unsigned char* __restrict__ ckm,
                 const int* __restrict__ cs_ids,
                 const int* __restrict__ use_cs_ids,
                 const float* __restrict__ embed,
                 float* __restrict__ out_enc,
                 float* __restrict__ out_mask,
                 float* __restrict__ out_ck_attn)
{
    const int n    = blockIdx.x >> 2;
    const int prt  = blockIdx.x & 3;
    const int tid  = threadIdx.x;
    const int wid  = tid >> 5;
    const int lane = tid & 31;
    const int j    = tid & 63;
    const int tq   = tid >> 6;
    __shared__ float scores[PK];
    __shared__ int   toks[16];
    __shared__ int   cs_sh;

    // Prolog on input-only data (safe before the dependency sync).
    const int use = *use_cs_ids;
    const int cs_id_n = cs_ids[n];

    // Wait for mega's g_ctx_use / g_know_use to be published.
    cudaGridDependencySynchronize();

    // ---- scores (redundant across the 4 parts; data is L2-hot) ----
    const float* __restrict__ cu = g_ctx_use + (size_t)n * PD;
    float cureg[8];
    #pragma unroll
    for (int c = 0; c < 8; c++) cureg[c] = cu[lane + 32 * c];

    #pragma unroll
    for (int kk = 0; kk < 4; kk++) {
        const int k = wid + kk * 8;
        const float* __restrict__ ku = g_know_use + ((size_t)n * PK + k) * PD;
        float p = 0.f;
        #pragma unroll
        for (int c = 0; c < 8; c++) p = fmaf(ku[lane + 32 * c], cureg[c], p);
        #pragma unroll
        for (int o = 16; o; o >>= 1) p += __shfl_xor_sync(0xFFFFFFFFu, p, o);
        if (lane == 0) scores[k] = p;
    }
    __syncthreads();

    if (tid == 0) {
        int best = 0;
        float bv = -__int_as_float(0x7f800000);  // -inf
        #pragma unroll
        for (int k = 0; k < PK; k++) {
            float v = ck_mask_at(ckm, n * PK + k) ? scores[k] : -__int_as_float(0x7f800000);
            if (v > bv) { bv = v; best = k; }   // first-max matches jnp.argmax
        }
        cs_sh = use ? cs_id_n : best;
    }
    if (prt == 0 && tid < PK) {
        bool cm = ck_mask_at(ckm, n * PK + tid);
        out_ck_attn[n * PK + tid] = cm ? scores[tid] : 0.0f;
    }
    __syncthreads();

    // ---- gather this part's 16 selected knowledge rows ----
    const int cs = cs_sh;
    const int tbase = prt * 16;
    if (tid < 16) toks[tid] = know_tokens[((size_t)n * PK + cs) * PTK + tbase + tid];
    __syncthreads();
    const bool cmn = ck_mask_at(ckm, n * PK + cs);
    const float4* __restrict__ e4 = (const float4*)embed;

    // 16 rows over 4 tq-groups -> 4 rows/thread-group, 4-deep batched.
    int   rows[4];
    float ws[4];
    float4 v[4];
    #pragma unroll
    for (int i = 0; i < 4; i++) {
        const int t = tq + 4 * i;              // local row 0..15
        const int tok = toks[t];
        const bool m = cmn && (tok != 0);
        ws[i]   = m ? 1.0f : 0.0f;
        rows[i] = m ? tok : 0;
    }
    #pragma unroll
    for (int i = 0; i < 4; i++) v[i] = __ldcg(&e4[(size_t)rows[i] * D4 + j]);
    #pragma unroll
    for (int i = 0; i < 4; i++) {
        const int t = tq + 4 * i;
        const size_t r = (size_t)n * FULL_T + tbase + t;
        __stcs(&((float4*)out_enc)[r * D4 + j],
               make_float4(ws[i] * v[i].x, ws[i] * v[i].y,
                           ws[i] * v[i].z, ws[i] * v[i].w));
    }
    if (tid < 16) {
        const int tok = toks[tid];
        out_mask[(size_t)n * FULL_T + tbase + tid] = (cmn && tok != 0) ? 1.0f : 0.0f;
    }
}

// ---------------------------------------------------------------------------
extern "C" void kernel_launch(void* const* d_in, const int* in_sizes, int n_in,
                              void* d_out, int out_size)
{
    const int*           src_tokens  = (const int*)d_in[0];            // [N,TC]
    const int*           know_tokens = (const int*)d_in[1];            // [N,K,TK]
    const unsigned char* ck_mask     = (const unsigned char*)d_in[2];  // [N,K] bool
    const int*           cs_ids      = (const int*)d_in[3];            // [N]
    const int*           use_cs_ids  = (const int*)d_in[4];            // scalar
    const float*         embed       = (const float*)d_in[5];          // [V,D]

    float* out = (float*)d_out;
    float* out_enc     = out;                                   // N*320*256
    float* out_mask    = out + (size_t)PN * FULL_T * PD;        // N*320
    float* out_ck_attn = out_mask + (size_t)PN * FULL_T;        // N*K

    mega_kernel<<<NB_MEGA, 256>>>(src_tokens, know_tokens, ck_mask, embed,
                                  out_enc, out_mask);

    // Tail via PDL: launches while mega drains; waits inside the kernel.
    cudaLaunchAttribute attrs[1];
    attrs[0].id = cudaLaunchAttributeProgrammaticStreamSerialization;
    attrs[0].val.programmaticStreamSerializationAllowed = 1;

    cudaLaunchConfig_t cfg = {};
    cfg.gridDim  = dim3(PN * 4, 1, 1);
    cfg.blockDim = dim3(256, 1, 1);
    cfg.dynamicSmemBytes = 0;
    cfg.stream = 0;                    // legacy default stream (capture target)
    cfg.attrs = attrs;
    cfg.numAttrs = 1;

    cudaError_t err = cudaLaunchKernelEx(&cfg, tail_kernel,
                                         know_tokens, ck_mask, cs_ids, use_cs_ids,
                                         embed, out_enc, out_mask, out_ck_attn);
    if (err != cudaSuccess) {
        // Fallback: plain launch (cudaGridDependencySynchronize is a no-op
        // when there is no programmatic dependency).
        tail_kernel<<<PN * 4, 256>>>(know_tokens, ck_mask, cs_ids, use_cs_ids,
                                     embed, out_enc, out_mask, out_ck_attn);
    }
}